// round 14
// baseline (speedup 1.0000x reference)
#include <cuda_runtime.h>

// PointPillarScatter: out[b,c,yi,xi] = feat[b,c,n*] where n* = max point index
// mapping to cell (yi,xi) in batch b (JAX scatter-set last-wins); 0 elsewhere.
// Index math replicates XLA: /0.16f -> *fp32(1/0.16f) == *6.25f exactly.
//
// R13 pipeline (best known) + doubled gather MLP in the fill role:
//   L0: init || min
//   L1: winner || T(b0)
//   Lk: T(bk) || F(bk-1)   k = 1..3   (Bresenham block interleave)
//   L4: F(b3)
// Fill threads now process cell-quads h and h+HV -> 8 independent 16B
// gathers in flight (latency hiding); all streaming accesses coalesced.

namespace {
constexpr int B  = 4;
constexpr int C  = 64;
constexpr int N  = 100000;
constexpr int NY = 496;
constexpr int NX = 432;
constexpr int CELLS  = NY * NX;        // 214272
constexpr int VCELLS = CELLS / 4;      // 53568 (float4 granularity)
constexpr int HV     = VCELLS / 2;     // 26784 (split-half stride, cell-quads)
constexpr int NV     = N / 4;          // 25000 point-quads
constexpr int SLOTS  = C / 4;          // 16 channel-quad groups per batch

constexpr int T_ITEMS  = SLOTS * NV;        // 400000
constexpr int F_ITEMS  = SLOTS * HV;        // 428544 (2 quads per thread)
constexpr int T_BLOCKS = (T_ITEMS + 255) / 256;   // 1563
constexpr int F_BLOCKS = F_ITEMS / 256;           // 1674 (exact)
constexpr int TF_BLOCKS = T_BLOCKS + F_BLOCKS;    // 3237

constexpr int I_BLOCKS = (B * VCELLS + 255) / 256;   // 837 init blocks
constexpr int M_PB     = 98;                          // min blocks per batch
constexpr int M_BLOCKS = M_PB * B;                    // 392
constexpr int W_PB     = (N + 255) / 256;             // 391 winner blocks/batch
constexpr int W_BLOCKS = W_PB * B;                    // 1564
}

// Scratch (no runtime allocation allowed).
__device__ __align__(16) int   g_winner[B * CELLS];
__device__ float g_minxy[B][2];
__device__ __align__(16) float g_buf[2][(size_t)SLOTS * N * 4];   // 2 x 25.6 MB

__device__ __forceinline__ void atomicMinF(float* addr, float v) {
    if (v >= 0.0f) atomicMin((int*)addr, __float_as_int(v));
    else           atomicMax((unsigned int*)addr, __float_as_uint(v));
}

// ── L0: init || min ──────────────────────────────────────────────────────
__device__ __forceinline__ void init_body(int blk) {
    int i = blk * 256 + threadIdx.x;
    if (i < B * VCELLS) reinterpret_cast<int4*>(g_winner)[i] = make_int4(-1, -1, -1, -1);
    if (i < B * 2) reinterpret_cast<float*>(g_minxy)[i] = __int_as_float(0x7f800000);
}

__device__ __forceinline__ void min_body(const float4* __restrict__ pts, int blk) {
    const int b = blk / M_PB;
    const int bx = blk % M_PB;
    const float INF = __int_as_float(0x7f800000);
    float mx = INF, my = INF;
    for (int n = bx * 256 + threadIdx.x; n < N; n += M_PB * 256) {
        float4 v = pts[b * N + n];
        mx = fminf(mx, v.y);
        my = fminf(my, v.z);
    }
    #pragma unroll
    for (int o = 16; o; o >>= 1) {
        mx = fminf(mx, __shfl_xor_sync(0xffffffffu, mx, o));
        my = fminf(my, __shfl_xor_sync(0xffffffffu, my, o));
    }
    __shared__ float sx[8], sy[8];
    const int warp = threadIdx.x >> 5, lane = threadIdx.x & 31;
    if (lane == 0) { sx[warp] = mx; sy[warp] = my; }
    __syncthreads();
    if (warp == 0) {
        mx = (lane < 8) ? sx[lane] : INF;
        my = (lane < 8) ? sy[lane] : INF;
        #pragma unroll
        for (int o = 4; o; o >>= 1) {
            mx = fminf(mx, __shfl_xor_sync(0xffffffffu, mx, o));
            my = fminf(my, __shfl_xor_sync(0xffffffffu, my, o));
        }
        if (lane == 0) {
            atomicMinF(&g_minxy[b][0], mx);
            atomicMinF(&g_minxy[b][1], my);
        }
    }
}

__global__ void __launch_bounds__(256) pp_initmin(const float4* __restrict__ pts) {
    const int bx = blockIdx.x;
    if (bx < I_BLOCKS) init_body(bx);
    else               min_body(pts, bx - I_BLOCKS);
}

// ── Winner role (last-wins via atomicMax on point index) ─────────────────
__device__ __forceinline__ void w_body(const float4* __restrict__ pts, int blk) {
    const int b = blk / W_PB;
    const int n = (blk % W_PB) * 256 + threadIdx.x;
    if (n >= N) return;
    float4 v = pts[b * N + n];
    const float R = 6.25f;                 // fp32(1/0.16f) == 6.25f (XLA rewrite)
    int xi = (int)floorf((v.y - g_minxy[b][0]) * R);
    int yi = (int)floorf((v.z - g_minxy[b][1]) * R);
    xi = min(max(xi, 0), NX - 1);
    yi = min(max(yi, 0), NY - 1);
    atomicMax(&g_winner[b * CELLS + yi * NX + xi], n);
}

// ── Transpose role: feat[b][slot*4+k][n] -> buf[b&1][slot][n][k] ─────────
__device__ __forceinline__ void t_body(const float* __restrict__ feat, int b, int blk) {
    int idx = blk * 256 + threadIdx.x;
    if (idx >= T_ITEMS) return;
    const int nv   = idx % NV;
    const int slot = idx / NV;
    const float4* base = reinterpret_cast<const float4*>(feat);
    const size_t row = ((size_t)b * C + slot * 4) * NV;
    float4 r0 = __ldcs(base + row + 0 * NV + nv);
    float4 r1 = __ldcs(base + row + 1 * NV + nv);
    float4 r2 = __ldcs(base + row + 2 * NV + nv);
    float4 r3 = __ldcs(base + row + 3 * NV + nv);
    float4* o = reinterpret_cast<float4*>(g_buf[b & 1]) + (size_t)slot * N + nv * 4;
    o[0] = make_float4(r0.x, r1.x, r2.x, r3.x);
    o[1] = make_float4(r0.y, r1.y, r2.y, r3.y);
    o[2] = make_float4(r0.z, r1.z, r2.z, r3.z);
    o[3] = make_float4(r0.w, r1.w, r2.w, r3.w);
}

// ── Fill role: 2 far-apart cell-quads per thread -> 8 independent 16B
//    gathers in flight; winner loads and output stores fully coalesced. ──
__device__ __forceinline__ void f_body(float4* __restrict__ out, int b, int blk) {
    int idx = blk * 256 + threadIdx.x;          // grid exact (F_ITEMS % 256 == 0)
    const int h    = idx % HV;
    const int slot = idx / HV;
    const int4* wp = reinterpret_cast<const int4*>(g_winner) + b * VCELLS;
    int4 w0 = wp[h];
    int4 w1 = wp[h + HV];
    const float4* fp = reinterpret_cast<const float4*>(g_buf[b & 1]) + (size_t)slot * N;
    const float4 z = make_float4(0.f, 0.f, 0.f, 0.f);
    float4 a0 = (w0.x >= 0) ? __ldg(fp + w0.x) : z;
    float4 a1 = (w0.y >= 0) ? __ldg(fp + w0.y) : z;
    float4 a2 = (w0.z >= 0) ? __ldg(fp + w0.z) : z;
    float4 a3 = (w0.w >= 0) ? __ldg(fp + w0.w) : z;
    float4 b0 = (w1.x >= 0) ? __ldg(fp + w1.x) : z;
    float4 b1 = (w1.y >= 0) ? __ldg(fp + w1.y) : z;
    float4 b2 = (w1.z >= 0) ? __ldg(fp + w1.z) : z;
    float4 b3 = (w1.w >= 0) ? __ldg(fp + w1.w) : z;
    float4* ob = out + ((size_t)b * C + slot * 4) * VCELLS;
    __stcs(ob + 0 * VCELLS + h,      make_float4(a0.x, a1.x, a2.x, a3.x));
    __stcs(ob + 1 * VCELLS + h,      make_float4(a0.y, a1.y, a2.y, a3.y));
    __stcs(ob + 2 * VCELLS + h,      make_float4(a0.z, a1.z, a2.z, a3.z));
    __stcs(ob + 3 * VCELLS + h,      make_float4(a0.w, a1.w, a2.w, a3.w));
    __stcs(ob + 0 * VCELLS + h + HV, make_float4(b0.x, b1.x, b2.x, b3.x));
    __stcs(ob + 1 * VCELLS + h + HV, make_float4(b0.y, b1.y, b2.y, b3.y));
    __stcs(ob + 2 * VCELLS + h + HV, make_float4(b0.z, b1.z, b2.z, b3.z));
    __stcs(ob + 3 * VCELLS + h + HV, make_float4(b0.w, b1.w, b2.w, b3.w));
}

// ── L1: winner || T(b0) ──────────────────────────────────────────────────
__global__ void __launch_bounds__(256) pp_wt0(const float4* __restrict__ pts,
                                              const float* __restrict__ feat) {
    const int bx = blockIdx.x;
    if (bx < W_BLOCKS) w_body(pts, bx);
    else               t_body(feat, 0, bx - W_BLOCKS);
}

// ── Lk: T(tb) || F(tb-1), Bresenham-interleaved roles ────────────────────
__global__ void __launch_bounds__(256) pp_tf(const float* __restrict__ feat,
                                             float4* __restrict__ out, int tb) {
    const int bx = blockIdx.x;
    int tBefore = (int)(((long long)bx * T_BLOCKS) / TF_BLOCKS);
    int tNext   = (int)(((long long)(bx + 1) * T_BLOCKS) / TF_BLOCKS);
    if (tNext > tBefore) t_body(feat, tb, tBefore);
    else                 f_body(out, tb - 1, bx - tBefore);
}

// ── L4: F(b3) ────────────────────────────────────────────────────────────
__global__ void __launch_bounds__(256) pp_ftail(float4* __restrict__ out) {
    f_body(out, 3, blockIdx.x);
}

extern "C" void kernel_launch(void* const* d_in, const int* in_sizes, int n_in,
                              void* d_out, int out_size) {
    (void)in_sizes; (void)n_in; (void)out_size;
    const float*  feat = (const float*)d_in[0];   // (B, C, N) f32
    const float4* pts  = (const float4*)d_in[1];  // (B*N, 4)  f32
    float4* out = (float4*)d_out;
    // d_in[2] (voxel_coords) unused by the reference computation.

    pp_initmin<<<I_BLOCKS + M_BLOCKS, 256>>>(pts);       // init || min
    pp_wt0<<<W_BLOCKS + T_BLOCKS, 256>>>(pts, feat);     // winner || T(b0)
    for (int b = 1; b < B; ++b)
        pp_tf<<<TF_BLOCKS, 256>>>(feat, out, b);         // T(b) || F(b-1)
    pp_ftail<<<F_BLOCKS, 256>>>(out);                    // F(b3)
}

// round 15
// speedup vs baseline: 1.0836x; 1.0836x over previous
#include <cuda_runtime.h>

// PointPillarScatter: out[b,c,yi,xi] = feat[b,c,n*] where n* = max point index
// mapping to cell (yi,xi) in batch b (JAX scatter-set last-wins); 0 elsewhere.
// Index math replicates XLA: /0.16f -> *fp32(1/0.16f) == *6.25f exactly.
//
// Cooperative-gather round. Scratch rows are full 256B: buf[n][64ch].
//  T role: 64x64 SMEM-tiled transpose (both global sides coalesced; output
//          rows contiguous -> 16KB streaming store per tile).
//  F role: 16 lanes fetch one cell's 256B row per instruction -> 2 L1
//          wavefronts/cell (vs 16 thread-private), SMEM tile (pad-65,
//          <=2-way conflicts) re-orders to cell-major for coalesced stores.
// Pipeline (R13): L0 init||min, L1 winner||T(b0), Lk T(bk)||F(bk-1), L4 F(b3).

namespace {
constexpr int B  = 4;
constexpr int C  = 64;
constexpr int N  = 100000;
constexpr int NY = 496;
constexpr int NX = 432;
constexpr int CELLS  = NY * NX;        // 214272
constexpr int VCELLS = CELLS / 4;      // 53568 (float4 granularity)
constexpr int NV     = N / 4;          // 25000 point-quads per channel

constexpr int T_PB = (N + 63) / 64;    // 1563 transpose tiles per batch
constexpr int F_PB = CELLS / 64;       // 3348 fill tiles per batch (exact)
constexpr int TF_BLOCKS = T_PB + F_PB; // 4911

constexpr int I_BLOCKS = (B * VCELLS + 255) / 256;   // 837 init blocks
constexpr int M_PB     = 98;                          // min blocks per batch
constexpr int M_BLOCKS = M_PB * B;                    // 392
constexpr int W_PB     = (N + 255) / 256;             // 391 winner blocks/batch
constexpr int W_BLOCKS = W_PB * B;                    // 1564
}

// Scratch (no runtime allocation allowed).
__device__ __align__(16) int   g_winner[B * CELLS];
__device__ float g_minxy[B][2];
__device__ __align__(16) float g_buf[2][(size_t)N * C];   // 2 x 25.6 MB row-major

__device__ __forceinline__ void atomicMinF(float* addr, float v) {
    if (v >= 0.0f) atomicMin((int*)addr, __float_as_int(v));
    else           atomicMax((unsigned int*)addr, __float_as_uint(v));
}

// ── L0: init || min ──────────────────────────────────────────────────────
__device__ __forceinline__ void init_body(int blk) {
    int i = blk * 256 + threadIdx.x;
    if (i < B * VCELLS) reinterpret_cast<int4*>(g_winner)[i] = make_int4(-1, -1, -1, -1);
    if (i < B * 2) reinterpret_cast<float*>(g_minxy)[i] = __int_as_float(0x7f800000);
}

__device__ __forceinline__ void min_body(const float4* __restrict__ pts, int blk) {
    const int b = blk / M_PB;
    const int bx = blk % M_PB;
    const float INF = __int_as_float(0x7f800000);
    float mx = INF, my = INF;
    for (int n = bx * 256 + threadIdx.x; n < N; n += M_PB * 256) {
        float4 v = pts[b * N + n];
        mx = fminf(mx, v.y);
        my = fminf(my, v.z);
    }
    #pragma unroll
    for (int o = 16; o; o >>= 1) {
        mx = fminf(mx, __shfl_xor_sync(0xffffffffu, mx, o));
        my = fminf(my, __shfl_xor_sync(0xffffffffu, my, o));
    }
    __shared__ float sx[8], sy[8];
    const int warp = threadIdx.x >> 5, lane = threadIdx.x & 31;
    if (lane == 0) { sx[warp] = mx; sy[warp] = my; }
    __syncthreads();
    if (warp == 0) {
        mx = (lane < 8) ? sx[lane] : INF;
        my = (lane < 8) ? sy[lane] : INF;
        #pragma unroll
        for (int o = 4; o; o >>= 1) {
            mx = fminf(mx, __shfl_xor_sync(0xffffffffu, mx, o));
            my = fminf(my, __shfl_xor_sync(0xffffffffu, my, o));
        }
        if (lane == 0) {
            atomicMinF(&g_minxy[b][0], mx);
            atomicMinF(&g_minxy[b][1], my);
        }
    }
}

__global__ void __launch_bounds__(256) pp_initmin(const float4* __restrict__ pts) {
    const int bx = blockIdx.x;
    if (bx < I_BLOCKS) init_body(bx);
    else               min_body(pts, bx - I_BLOCKS);
}

// ── Winner role (last-wins via atomicMax on point index) ─────────────────
__device__ __forceinline__ void w_body(const float4* __restrict__ pts, int blk) {
    const int b = blk / W_PB;
    const int n = (blk % W_PB) * 256 + threadIdx.x;
    if (n >= N) return;
    float4 v = pts[b * N + n];
    const float R = 6.25f;                 // fp32(1/0.16f) == 6.25f (XLA rewrite)
    int xi = (int)floorf((v.y - g_minxy[b][0]) * R);
    int yi = (int)floorf((v.z - g_minxy[b][1]) * R);
    xi = min(max(xi, 0), NX - 1);
    yi = min(max(yi, 0), NY - 1);
    atomicMax(&g_winner[b * CELLS + yi * NX + xi], n);
}

// ── Transpose role: 64-point x 64-channel SMEM tile.
//    Load feat[b][c][n0..n0+63] (coalesced) -> S[n_local][c] (pad-65)
//    -> store buf rows [n][0..63] (contiguous 16KB per tile). ─────────────
__device__ __forceinline__ void t_body(const float* __restrict__ feat, int b,
                                       int blk, float* S) {
    const int t = threadIdx.x;
    const int n0 = blk * 64;
    const float4* f4 = reinterpret_cast<const float4*>(feat);
    #pragma unroll
    for (int i = 0; i < 4; ++i) {
        int item = i * 256 + t;            // 1024 items
        int c = item >> 4;                 // channel 0..63
        int j = item & 15;                 // f4 index within 64 points
        int nf = (n0 >> 2) + j;
        if (nf < NV) {
            float4 v = __ldcs(f4 + ((size_t)b * C + c) * NV + nf);
            int nl = j * 4;
            S[(nl + 0) * 65 + c] = v.x;
            S[(nl + 1) * 65 + c] = v.y;
            S[(nl + 2) * 65 + c] = v.z;
            S[(nl + 3) * 65 + c] = v.w;
        }
    }
    __syncthreads();
    float4* o = reinterpret_cast<float4*>(g_buf[b & 1]);
    #pragma unroll
    for (int i = 0; i < 4; ++i) {
        int item = i * 256 + t;
        int nl = item >> 4;                // local point 0..63
        int cf = item & 15;                // channel f4 0..15
        int n = n0 + nl;
        if (n < N) {
            float4 v = make_float4(S[nl * 65 + 4 * cf + 0],
                                   S[nl * 65 + 4 * cf + 1],
                                   S[nl * 65 + 4 * cf + 2],
                                   S[nl * 65 + 4 * cf + 3]);
            o[(size_t)n * 16 + cf] = v;
        }
    }
}

// ── Fill role: 64 cells per block. 16 lanes fetch one cell's 256B row per
//    instruction (2 wavefronts/cell); SMEM pad-65 tile re-orders to
//    cell-major; 64 channels x 16 f4 coalesced streaming stores. ──────────
__device__ __forceinline__ void f_body(float4* __restrict__ out, int b,
                                       int blk, float* S, int* w_s) {
    const int t = threadIdx.x;
    if (t < 16)
        reinterpret_cast<int4*>(w_s)[t] =
            reinterpret_cast<const int4*>(g_winner + b * CELLS)[blk * 16 + t];
    __syncthreads();
    const float4* fp = reinterpret_cast<const float4*>(g_buf[b & 1]);
    const float4 z = make_float4(0.f, 0.f, 0.f, 0.f);
    #pragma unroll
    for (int i = 0; i < 4; ++i) {
        int item = i * 256 + t;            // 1024 items
        int cell  = item >> 4;             // 0..63
        int chunk = item & 15;             // channel f4 0..15
        int n = w_s[cell];
        float4 v = (n >= 0) ? __ldg(fp + (size_t)n * 16 + chunk) : z;
        S[cell * 65 + 4 * chunk + 0] = v.x;
        S[cell * 65 + 4 * chunk + 1] = v.y;
        S[cell * 65 + 4 * chunk + 2] = v.z;
        S[cell * 65 + 4 * chunk + 3] = v.w;
    }
    __syncthreads();
    #pragma unroll
    for (int i = 0; i < 4; ++i) {
        int item = i * 256 + t;
        int c = item >> 4;                 // channel 0..63
        int j = item & 15;                 // cell f4 0..15
        float4 v = make_float4(S[(4 * j + 0) * 65 + c],
                               S[(4 * j + 1) * 65 + c],
                               S[(4 * j + 2) * 65 + c],
                               S[(4 * j + 3) * 65 + c]);
        __stcs(out + ((size_t)b * C + c) * VCELLS + blk * 16 + j, v);
    }
}

// ── L1: winner || T(b0) ──────────────────────────────────────────────────
__global__ void __launch_bounds__(256) pp_wt0(const float4* __restrict__ pts,
                                              const float* __restrict__ feat) {
    __shared__ float S[64 * 65];
    const int bx = blockIdx.x;
    if (bx < W_BLOCKS) w_body(pts, bx);
    else               t_body(feat, 0, bx - W_BLOCKS, S);
}

// ── Lk: T(tb) || F(tb-1), Bresenham-interleaved roles ────────────────────
__global__ void __launch_bounds__(256) pp_tf(const float* __restrict__ feat,
                                             float4* __restrict__ out, int tb) {
    __shared__ float S[64 * 65];
    __shared__ int w_s[64];
    const int bx = blockIdx.x;
    int tBefore = (int)(((long long)bx * T_PB) / TF_BLOCKS);
    int tNext   = (int)(((long long)(bx + 1) * T_PB) / TF_BLOCKS);
    if (tNext > tBefore) t_body(feat, tb, tBefore, S);
    else                 f_body(out, tb - 1, bx - tBefore, S, w_s);
}

// ── L4: F(b3) ────────────────────────────────────────────────────────────
__global__ void __launch_bounds__(256) pp_ftail(float4* __restrict__ out) {
    __shared__ float S[64 * 65];
    __shared__ int w_s[64];
    f_body(out, 3, blockIdx.x, S, w_s);
}

extern "C" void kernel_launch(void* const* d_in, const int* in_sizes, int n_in,
                              void* d_out, int out_size) {
    (void)in_sizes; (void)n_in; (void)out_size;
    const float*  feat = (const float*)d_in[0];   // (B, C, N) f32
    const float4* pts  = (const float4*)d_in[1];  // (B*N, 4)  f32
    float4* out = (float4*)d_out;
    // d_in[2] (voxel_coords) unused by the reference computation.

    pp_initmin<<<I_BLOCKS + M_BLOCKS, 256>>>(pts);       // init || min
    pp_wt0<<<W_BLOCKS + T_PB, 256>>>(pts, feat);         // winner || T(b0)
    for (int b = 1; b < B; ++b)
        pp_tf<<<TF_BLOCKS, 256>>>(feat, out, b);         // T(b) || F(b-1)
    pp_ftail<<<F_PB, 256>>>(out);                        // F(b3)
}